// round 14
// baseline (speedup 1.0000x reference)
#include <cuda_runtime.h>
#include <stdint.h>
#include <cub/block/block_radix_sort.cuh>

// Shapes (fixed): seq (16,4096,1024) f32, attn_weights (16,4096) f32,
// out (16,2049,1024) f32.
#define BB 16
#define NN 4096
#define DD 1024
#define KK 2048
#define D4 (DD / 4)
#define CHUNK 512                     // elements per chunk-sort CTA
#define NRUNS (NN / CHUNK)            // 8 sorted runs per batch
#define GROUP 16                      // rows per copy CTA
#define SELGROUPS (KK / GROUP)        // 128 copy CTAs per batch
#define PR_GROUP 64                   // rows per pruned-sum CTA
#define PRCH (KK / PR_GROUP)          // 32 pruned partials per batch
#define GATHER_CTAS (PRCH + SELGROUPS)   // 160 gather CTAs per batch
#define ROLES (NRUNS + GATHER_CTAS)      // 168 roles per batch

typedef unsigned long long u64;

__device__ u64   g_run[BB * NN];               // chunk-sorted composite keys
__device__ int   g_sorted[BB * NN];
__device__ float g_partial[BB * PRCH * DD];    // 2 MB scratch
__device__ int   g_cntA[BB];                   // runs-published tickets
__device__ int   g_cntB[BB];                   // ranks-published tickets
__device__ int   g_cntC[BB];                   // gather-completion tickets
__device__ int   g_cntMix[BB];                 // mix tickets (self-resetting)

// Spin until *p >= target (t0 polls with backoff), then acquire-fence the CTA.
__device__ __forceinline__ void spin_until(volatile int* p, int target) {
    if (threadIdx.x == 0) {
        while (*p < target) __nanosleep(64);
    }
    __syncthreads();
    __threadfence();   // acquire: order subsequent reads after the observation
}

// ---------------------------------------------------------------------------
// Single fused kernel. Grid (BB, ROLES), role-major on blockIdx.y so ALL
// sort CTAs (y < NRUNS) occupy the lowest linear block IDs -> scheduled in
// wave 1 (producers always resident; consumers spin with backoff -> no
// starvation). Per-batch flags pipeline rank -> gather across batches.
//
// Roles:
//  y in [0, NRUNS):          sort run y of batch x (CUB 256x2 radix, stable,
//                            key = ~mono(f32): composite u64 order matches
//                            jax.lax.top_k), then after all 8 runs of this
//                            batch land, rank OWN chunk's 512 elements via
//                            7 interleaved smem binary searches (+ exact
//                            correction probe) and scatter to g_sorted.
//  y-NRUNS in [0, PRCH):     sum 64 pruned rows -> partial; last arriver
//                            reduces 32 partials -> mix row (row KK).
//  y-NRUNS in [PRCH, 168):   copy 16 selected rows (two 8-row batches, 8
//                            outstanding loads/thread).
// All tickets use release-fence -> atomic -> acquire-fence; counters are
// reset by the per-batch completion ticket (graph-replay safe).
// ---------------------------------------------------------------------------
__global__ __launch_bounds__(256) void fused_kernel(const float* __restrict__ w,
                                                    const float4* __restrict__ seq,
                                                    float4* __restrict__ out) {
    typedef cub::BlockRadixSort<unsigned int, 256, 2, int, 5> Sorter;
    __shared__ union SU {
        typename Sorter::TempStorage sort_temp;
        u64 runs[NN];                                   // 32 KB
        struct { int toks[PR_GROUP]; int ticket; } gth;
    } su;
    static_assert(sizeof(typename Sorter::TempStorage) <= sizeof(u64) * NN, "smem");

    const int b = blockIdx.x;
    const int role = blockIdx.y;
    const int t = threadIdx.x;

    if (role < NRUNS) {
        // ---------------- sort + rank ----------------
        const int c = role;
        unsigned int keys[2];
        int vals[2];
#pragma unroll
        for (int p = 0; p < 2; p++) {
            int i = c * CHUNK + 2 * t + p;
            unsigned int u = __float_as_uint(w[b * NN + i]);
            unsigned int mono = (u & 0x80000000u) ? ~u : (u | 0x80000000u);
            keys[p] = ~mono;
            vals[p] = i;
        }
        Sorter(su.sort_temp).Sort(keys, vals);   // stable, blocked

#pragma unroll
        for (int p = 0; p < 2; p++)
            g_run[b * NN + c * CHUNK + 2 * t + p] =
                ((u64)keys[p] << 32) | (unsigned int)vals[p];

        // release run, ticket, wait for all 8 runs of this batch
        __threadfence();
        __syncthreads();
        if (t == 0) atomicAdd(&g_cntA[b], 1);
        spin_until(&g_cntA[b], NRUNS);

        // stage all 8 runs into smem (sort temp dead -> union reuse)
        const u64* base = g_run + b * NN;
#pragma unroll
        for (int s = 0; s < NN / 256; s++)
            su.runs[t + s * 256] = __ldcg(base + t + s * 256);
        __syncthreads();

        // rank own chunk: 2 elements/thread, 7 interleaved searches each
#pragma unroll
        for (int e = 0; e < 2; e++) {
            const int p = t + e * 256;              // 0..511 within own run
            const u64 key = su.runs[c * CHUNK + p];

            const u64* A[7];
            int cnt[7];
#pragma unroll
            for (int q = 0; q < 7; q++) {
                A[q] = su.runs + (((c + 1 + q) & 7) << 9);
                cnt[q] = 0;
            }
#pragma unroll
            for (int step = CHUNK / 2; step > 0; step >>= 1) {
#pragma unroll
                for (int q = 0; q < 7; q++)
                    if (A[q][cnt[q] + step - 1] < key) cnt[q] += step;
            }
#pragma unroll
            for (int q = 0; q < 7; q++)             // exact lower_bound fixup
                if (A[q][cnt[q]] < key) cnt[q]++;

            int rank = p;
#pragma unroll
            for (int q = 0; q < 7; q++) rank += cnt[q];
            g_sorted[b * NN + rank] = (int)(key & 0xFFFFFFFFu);
        }

        // release ranks
        __threadfence();
        __syncthreads();
        if (t == 0) atomicAdd(&g_cntB[b], 1);
        return;
    }

    // ---------------- gather / sum / mix ----------------
    const int g = role - NRUNS;
    spin_until(&g_cntB[b], NRUNS);      // wait: this batch's ranks published

    const float4* sb = seq + (size_t)b * NN * D4;

    if (g < PRCH) {
        // pruned-sum CTA: sorted positions [KK + g*64, KK + (g+1)*64)
        if (t < PR_GROUP) su.gth.toks[t] = __ldcg(&g_sorted[b * NN + KK + g * PR_GROUP + t]);
        __syncthreads();

        float4 acc = make_float4(0.f, 0.f, 0.f, 0.f);
#pragma unroll 8
        for (int k = 0; k < PR_GROUP; k++) {
            float4 v = __ldcs(sb + (size_t)su.gth.toks[k] * D4 + t);
            acc.x += v.x; acc.y += v.y; acc.z += v.z; acc.w += v.w;
        }
        float4* part = reinterpret_cast<float4*>(g_partial);
        part[((size_t)b * PRCH + g) * D4 + t] = acc;

        // release partial, ticket; last arriver reduces into the mix row
        __threadfence();
        if (t == 0) su.gth.ticket = atomicAdd(&g_cntMix[b], 1);
        __syncthreads();
        if (su.gth.ticket == PRCH - 1) {
            __threadfence();            // acquire
            const float4* pbase = part + (size_t)b * PRCH * D4 + t;
            float4 s = make_float4(0.f, 0.f, 0.f, 0.f);
#pragma unroll
            for (int c2 = 0; c2 < PRCH; c2++) {
                float4 v = __ldcg(pbase + (size_t)c2 * D4);
                s.x += v.x; s.y += v.y; s.z += v.z; s.w += v.w;
            }
            const float scale = 0.05f / (2048.0f + 1e-10f);
            s.x *= scale; s.y *= scale; s.z *= scale; s.w *= scale;
            out[((size_t)b * (KK + 1) + KK) * D4 + t] = s;
            if (t == 0) g_cntMix[b] = 0;
        }
    } else {
        // copy CTA: sorted positions [j0, j0+16), two 8-row batches (MLP=8)
        const int j0 = (g - PRCH) * GROUP;
        if (t < GROUP) su.gth.toks[t] = __ldcg(&g_sorted[b * NN + j0 + t]);
        __syncthreads();

        float4* dst = out + ((size_t)b * (KK + 1) + j0) * D4 + t;
#pragma unroll
        for (int h = 0; h < 2; h++) {
            float4 v[8];
#pragma unroll
            for (int k = 0; k < 8; k++)
                v[k] = __ldcs(sb + (size_t)su.gth.toks[h * 8 + k] * D4 + t);
#pragma unroll
            for (int k = 0; k < 8; k++)
                __stcs(dst + (size_t)(h * 8 + k) * D4, v[k]);
        }
    }

    // completion ticket: last gather CTA of this batch resets the counters
    __syncthreads();
    if (t == 0) {
        int done = atomicAdd(&g_cntC[b], 1);
        if (done == GATHER_CTAS - 1) {
            g_cntA[b] = 0;
            g_cntB[b] = 0;
            g_cntC[b] = 0;
        }
    }
}

// ---------------------------------------------------------------------------
extern "C" void kernel_launch(void* const* d_in, const int* in_sizes, int n_in,
                              void* d_out, int out_size) {
    const float* seq = (const float*)d_in[0];
    const float* attn_weights = (const float*)d_in[1];
    float* out = (float*)d_out;
    (void)in_sizes; (void)n_in; (void)out_size;

    dim3 grid(BB, ROLES);    // (16, 168); role-major y => sort CTAs first
    fused_kernel<<<grid, 256>>>(attn_weights, (const float4*)seq, (float4*)out);
}

// round 15
// speedup vs baseline: 1.1119x; 1.1119x over previous
#include <cuda_runtime.h>
#include <stdint.h>
#include <cub/block/block_radix_sort.cuh>

// Shapes (fixed): seq (16,4096,1024) f32, attn_weights (16,4096) f32,
// out (16,2049,1024) f32.
#define BB 16
#define NN 4096
#define DD 1024
#define KK 2048
#define D4 (DD / 4)
#define CHUNK 512                     // elements per chunk-sort CTA
#define NRUNS (NN / CHUNK)            // 8 sorted runs per batch
#define GROUP 16                      // rows per copy CTA
#define SELGROUPS (KK / GROUP)        // 128 copy CTAs per batch
#define PR_GROUP 64                   // rows per pruned-sum CTA
#define PRCH (KK / PR_GROUP)          // 32 pruned partials per batch

typedef unsigned long long u64;

__device__ u64   g_run[BB * NN];               // chunk-sorted composite keys
__device__ int   g_sorted[BB * NN];
__device__ float g_partial[BB * PRCH * DD];    // 2 MB scratch
__device__ int   g_cntA[BB];                   // runs-published tickets
__device__ int   g_cntB[BB];                   // rank-done tickets (for reset)
__device__ int   g_cntMix[BB];                 // mix tickets (self-resetting)

// ---------------------------------------------------------------------------
// Fused sort+rank. Grid (8, BB) = 128 CTAs -- all resident in wave 1
// (128 < 148 SMs), so the intra-batch spin is deadlock-free and only pays
// the tiny sort-skew between sibling CTAs.
// Each CTA: CUB 256x2 stable radix sort of its 512-chunk (key = ~mono(f32):
// ascending u32 == descending weight; stability => ascending index on ties;
// packed u64 = (key<<32)|idx is unique and ordered exactly like
// jax.lax.top_k). Publish run (release+ticket), spin for the batch's 8 runs
// (acquire), stage all runs in smem (reusing the sort temp union), rank own
// 512 elements (2/thread): local pos + 7 exact lower_bound counts via
// interleaved fixed-step searches + correction probe; scatter to g_sorted.
// Second ticket resets both counters for graph replay.
// ---------------------------------------------------------------------------
__global__ __launch_bounds__(256) void sort_rank_kernel(const float* __restrict__ w) {
    typedef cub::BlockRadixSort<unsigned int, 256, 2, int, 5> Sorter;
    __shared__ union SU {
        typename Sorter::TempStorage sort_temp;
        u64 runs[NN];                                   // 32 KB
    } su;
    static_assert(sizeof(typename Sorter::TempStorage) <= sizeof(u64) * NN, "smem");

    const int b = blockIdx.y;
    const int c = blockIdx.x;
    const int t = threadIdx.x;

    unsigned int keys[2];
    int vals[2];
#pragma unroll
    for (int p = 0; p < 2; p++) {
        int i = c * CHUNK + 2 * t + p;
        unsigned int u = __float_as_uint(w[b * NN + i]);
        unsigned int mono = (u & 0x80000000u) ? ~u : (u | 0x80000000u);
        keys[p] = ~mono;
        vals[p] = i;
    }
    Sorter(su.sort_temp).Sort(keys, vals);   // stable, blocked

#pragma unroll
    for (int p = 0; p < 2; p++)
        g_run[b * NN + c * CHUNK + 2 * t + p] =
            ((u64)keys[p] << 32) | (unsigned int)vals[p];

    // release own run, ticket, spin for all 8 runs of this batch
    __threadfence();
    __syncthreads();
    if (t == 0) {
        atomicAdd(&g_cntA[b], 1);
        volatile int* pa = &g_cntA[b];
        while (*pa < NRUNS) __nanosleep(32);
    }
    __syncthreads();
    __threadfence();   // acquire: order run reads after observation

    // stage all 8 runs into smem (sort temp is dead -> union reuse)
    const u64* base = g_run + b * NN;
#pragma unroll
    for (int s = 0; s < NN / 256; s++)
        su.runs[t + s * 256] = __ldcg(base + t + s * 256);
    __syncthreads();

    // rank own chunk: 2 elements/thread, 7 interleaved LDS searches each
#pragma unroll
    for (int e = 0; e < 2; e++) {
        const int p = t + e * 256;              // 0..511 within own run
        const u64 key = su.runs[c * CHUNK + p];

        const u64* A[7];
        int cnt[7];
#pragma unroll
        for (int q = 0; q < 7; q++) {
            A[q] = su.runs + (((c + 1 + q) & 7) << 9);
            cnt[q] = 0;
        }
#pragma unroll
        for (int step = CHUNK / 2; step > 0; step >>= 1) {
#pragma unroll
            for (int q = 0; q < 7; q++)
                if (A[q][cnt[q] + step - 1] < key) cnt[q] += step;
        }
#pragma unroll
        for (int q = 0; q < 7; q++)             // exact lower_bound fixup
            if (A[q][cnt[q]] < key) cnt[q]++;

        int rank = p;
#pragma unroll
        for (int q = 0; q < 7; q++) rank += cnt[q];
        g_sorted[b * NN + rank] = (int)(key & 0xFFFFFFFFu);
    }

    // completion ticket: last CTA of the batch resets counters (graph replay)
    __syncthreads();
    if (t == 0) {
        int done = atomicAdd(&g_cntB[b], 1);
        if (done == NRUNS - 1) {
            g_cntA[b] = 0;
            g_cntB[b] = 0;
        }
    }
}

// ---------------------------------------------------------------------------
// Fused gather/sum/mix (unchanged from the 76.3us best): asymmetric grid,
// per batch blocks [0,PRCH) sum 64 pruned rows -> partial (first => longest
// run first); last arriver (release+ticket+acquire) reduces 32 L2-resident
// partials into the mix row. Blocks [PRCH,160) copy 16 selected rows each,
// two 8-row batches (MLP=8 beats occupancy here). Streaming accesses.
// ---------------------------------------------------------------------------
__global__ __launch_bounds__(256) void gather_sum_kernel(const float4* __restrict__ seq,
                                                         float4* __restrict__ out) {
    const int b = blockIdx.y;
    const int g = blockIdx.x;
    const int tid = threadIdx.x;

    const float4* sb = seq + (size_t)b * NN * D4;

    if (g < PRCH) {
        __shared__ int toks[PR_GROUP];
        __shared__ int ticket;
        if (tid < PR_GROUP) toks[tid] = g_sorted[b * NN + KK + g * PR_GROUP + tid];
        __syncthreads();

        float4 acc = make_float4(0.f, 0.f, 0.f, 0.f);
#pragma unroll 8
        for (int t = 0; t < PR_GROUP; t++) {
            float4 v = __ldcs(sb + (size_t)toks[t] * D4 + tid);
            acc.x += v.x; acc.y += v.y; acc.z += v.z; acc.w += v.w;
        }
        float4* part = reinterpret_cast<float4*>(g_partial);
        part[((size_t)b * PRCH + g) * D4 + tid] = acc;

        // release partial, ticket; last arriver reduces into the mix row
        __threadfence();
        if (tid == 0) ticket = atomicAdd(&g_cntMix[b], 1);
        __syncthreads();
        if (ticket == PRCH - 1) {
            __threadfence();            // acquire
            const float4* pbase = part + (size_t)b * PRCH * D4 + tid;
            float4 s = make_float4(0.f, 0.f, 0.f, 0.f);
#pragma unroll
            for (int c = 0; c < PRCH; c++) {
                float4 v = __ldcg(pbase + (size_t)c * D4);
                s.x += v.x; s.y += v.y; s.z += v.z; s.w += v.w;
            }
            const float scale = 0.05f / (2048.0f + 1e-10f);
            s.x *= scale; s.y *= scale; s.z *= scale; s.w *= scale;
            out[((size_t)b * (KK + 1) + KK) * D4 + tid] = s;
            if (tid == 0) g_cntMix[b] = 0;   // reset for next graph replay
        }
    } else {
        const int j0 = (g - PRCH) * GROUP;
        __shared__ int toks[GROUP];
        if (tid < GROUP) toks[tid] = g_sorted[b * NN + j0 + tid];
        __syncthreads();

        float4* dst = out + ((size_t)b * (KK + 1) + j0) * D4 + tid;
#pragma unroll
        for (int h = 0; h < 2; h++) {
            float4 v[8];
#pragma unroll
            for (int t = 0; t < 8; t++)
                v[t] = __ldcs(sb + (size_t)toks[h * 8 + t] * D4 + tid);
#pragma unroll
            for (int t = 0; t < 8; t++)
                __stcs(dst + (size_t)(h * 8 + t) * D4, v[t]);
        }
    }
}

// ---------------------------------------------------------------------------
extern "C" void kernel_launch(void* const* d_in, const int* in_sizes, int n_in,
                              void* d_out, int out_size) {
    const float* seq = (const float*)d_in[0];
    const float* attn_weights = (const float*)d_in[1];
    float* out = (float*)d_out;
    (void)in_sizes; (void)n_in; (void)out_size;

    dim3 sgrid(NRUNS, BB);                // (8, 16) = 128 CTAs, all wave-1
    sort_rank_kernel<<<sgrid, 256>>>(attn_weights);

    dim3 fgrid(PRCH + SELGROUPS, BB);     // (160, 16)
    gather_sum_kernel<<<fgrid, 256>>>((const float4*)seq, (float4*)out);
}